// round 15
// baseline (speedup 1.0000x reference)
#include <cuda_runtime.h>
#include <cuda_bf16.h>
#include <cstdint>

#define Nn   100000
#define Emax 1600000
#define DIN  512
#define H1h  8
#define C1   128   // H1*D1
#define D2   64
#define SLOPE 0.2f
#define SCAN_B 1024

// ---------------- scratch (device globals; no allocs allowed) ----------------
__device__ float g_ft1[(size_t)Nn * C1];
__device__ float g_el1[Nn * H1h];
__device__ float g_er1[Nn * H1h];
__device__ float g_ft2[(size_t)Nn * D2];
__device__ float g_el2[Nn];
__device__ float g_er2[Nn];

__device__ __nv_bfloat16 g_W1h[C1 * DIN];
__device__ __nv_bfloat16 g_W1l[C1 * DIN];
__device__ __nv_bfloat16 g_W2h[D2 * C1];
__device__ __nv_bfloat16 g_W2l[D2 * C1];

__device__ int g_hist[Nn];
__device__ int g_scan[Nn];
__device__ int g_bsum[128];
__device__ int g_boff[128];
__device__ int g_rowstart[Nn];
__device__ int g_cursor[Nn];
__device__ int g_ssrc[Emax];

// ================= helpers =================
__device__ __forceinline__ uint32_t smem_u32(const void* p) {
    uint32_t a;
    asm("{ .reg .u64 t; cvta.to.shared.u64 t, %1; cvt.u32.u64 %0, t; }" : "=r"(a) : "l"(p));
    return a;
}
__device__ __forceinline__ void ldsm4(uint32_t* r, uint32_t addr) {
    asm volatile("ldmatrix.sync.aligned.m8n8.x4.shared.b16 {%0,%1,%2,%3}, [%4];"
        : "=r"(r[0]), "=r"(r[1]), "=r"(r[2]), "=r"(r[3]) : "r"(addr));
}
__device__ __forceinline__ void mma_bf16(float* d, const uint32_t* a, const uint32_t* b) {
    asm volatile("mma.sync.aligned.m16n8k16.row.col.f32.bf16.bf16.f32 "
        "{%0,%1,%2,%3}, {%4,%5,%6,%7}, {%8,%9}, {%0,%1,%2,%3};"
        : "+f"(d[0]), "+f"(d[1]), "+f"(d[2]), "+f"(d[3])
        : "r"(a[0]), "r"(a[1]), "r"(a[2]), "r"(a[3]), "r"(b[0]), "r"(b[1]));
}
__device__ __forceinline__ void split_pair(float x, float y, uint32_t& hi, uint32_t& lo) {
    __nv_bfloat16 hx = __float2bfloat16(x), hy = __float2bfloat16(y);
    __nv_bfloat16 lx = __float2bfloat16(x - __bfloat162float(hx));
    __nv_bfloat16 ly = __float2bfloat16(y - __bfloat162float(hy));
    __nv_bfloat162 h(hx, hy), l(lx, ly);
    hi = *(uint32_t*)&h;
    lo = *(uint32_t*)&l;
}

// ================= pre-split weights =================
__global__ void splitW_kernel(const float* __restrict__ W1, const float* __restrict__ W2) {
    int i = blockIdx.x * blockDim.x + threadIdx.x;
    if (i < C1 * DIN) {
        float v = W1[i];
        __nv_bfloat16 h = __float2bfloat16(v);
        g_W1h[i] = h;
        g_W1l[i] = __float2bfloat16(v - __bfloat162float(h));
    }
    int j = i - C1 * DIN;
    if (j >= 0 && j < D2 * C1) {
        float v = W2[j];
        __nv_bfloat16 h = __float2bfloat16(v);
        g_W2h[j] = h;
        g_W2l[j] = __float2bfloat16(v - __bfloat162float(h));
    }
}

// ================= counting sort by dst (+ zero el2/er2 for gemm2 atomics) =====
__global__ void zero_hist(int n) {
    int i = blockIdx.x * blockDim.x + threadIdx.x;
    if (i < n) { g_hist[i] = 0; g_el2[i] = 0.f; g_er2[i] = 0.f; }
}
__global__ void hist_kernel(const int* __restrict__ dst, int E) {
    int e = blockIdx.x * blockDim.x + threadIdx.x;
    if (e < E) atomicAdd(&g_hist[dst[e]], 1);
}
__global__ void scanA(int n) {
    __shared__ int sm[SCAN_B];
    int idx = blockIdx.x * SCAN_B + threadIdx.x;
    int v = (idx < n) ? g_hist[idx] : 0;
    sm[threadIdx.x] = v;
    __syncthreads();
#pragma unroll
    for (int off = 1; off < SCAN_B; off <<= 1) {
        int t = (threadIdx.x >= off) ? sm[threadIdx.x - off] : 0;
        __syncthreads();
        sm[threadIdx.x] += t;
        __syncthreads();
    }
    if (idx < n) g_scan[idx] = sm[threadIdx.x];
    if (threadIdx.x == SCAN_B - 1) g_bsum[blockIdx.x] = sm[threadIdx.x];
}
__global__ void scanB(int nb) {
    __shared__ int sm[128];
    int v = (threadIdx.x < nb) ? g_bsum[threadIdx.x] : 0;
    sm[threadIdx.x] = v;
    __syncthreads();
#pragma unroll
    for (int off = 1; off < 128; off <<= 1) {
        int t = (threadIdx.x >= off) ? sm[threadIdx.x - off] : 0;
        __syncthreads();
        sm[threadIdx.x] += t;
        __syncthreads();
    }
    if (threadIdx.x < nb) g_boff[threadIdx.x] = sm[threadIdx.x] - v;
}
__global__ void scanC(int n) {
    int idx = blockIdx.x * blockDim.x + threadIdx.x;
    if (idx < n) {
        int ex = g_scan[idx] - g_hist[idx] + g_boff[idx >> 10];
        g_rowstart[idx] = ex;
        g_cursor[idx]   = ex;
    }
}
__global__ void scatter_kernel(const int* __restrict__ src, const int* __restrict__ dst, int E) {
    int e = blockIdx.x * blockDim.x + threadIdx.x;
    if (e < E) {
        int d = dst[e];
        int pos = atomicAdd(&g_cursor[d], 1);
        g_ssrc[pos] = src[e];
    }
}

// ================= tensor-core GEMM1 via mma.sync (split-bf16) =================
// Round-11 structure; ONE change: __launch_bounds__(256, 2) caps registers so
// 2 CTAs co-reside per SM (profile showed occ=22.7% => 1 CTA/SM at regs=128;
// the kernel is latency-bound with tensor=53%).
#define KC1    64
#define NCH1   (DIN / KC1)     // 8 chunks
#define LDE1   72              // padded row stride in bf16 elems (144 B)
#define ROWB1  (LDE1 * 2)
#define G1_SMEM (4 * 128 * ROWB1)   // 73728 B

__global__ void __launch_bounds__(256, 2) gemm1_mma_kernel(
    const float* __restrict__ A,
    const float* __restrict__ al1, const float* __restrict__ ar1, int n)
{
    extern __shared__ __align__(16) char sm1[];
    const uint32_t sAh = smem_u32(sm1);
    const uint32_t sAl = sAh + 128 * ROWB1;
    const uint32_t sWh = sAl + 128 * ROWB1;
    const uint32_t sWl = sWh + 128 * ROWB1;
    char* pAh = sm1;
    char* pAl = sm1 + 128 * ROWB1;
    char* pWh = sm1 + 2 * 128 * ROWB1;
    char* pWl = sm1 + 3 * 128 * ROWB1;

    const int tid = threadIdx.x;
    const int lane = tid & 31, wid = tid >> 5;
    const int wm = wid >> 2, wn = wid & 3;         // 2 x 4 warp grid
    const int row0 = blockIdx.x * 128;

    float acc[4][4][4];
#pragma unroll
    for (int m = 0; m < 4; m++)
#pragma unroll
        for (int q = 0; q < 4; q++)
#pragma unroll
            for (int r = 0; r < 4; r++) acc[m][q][r] = 0.f;

    for (int c = 0; c < NCH1; c++) {
        const int k0 = c * KC1;
        __syncthreads();
        // load + split A: 2048 float4 / 256 thr = 8 each; uint2 (STS.64) stores
#pragma unroll
        for (int i = tid; i < 2048; i += 256) {
            int r = i >> 4, c4 = i & 15;
            int row = row0 + r;
            float4 v = (row < n) ? *(const float4*)(A + (size_t)row * DIN + k0 + c4 * 4)
                                 : make_float4(0.f, 0.f, 0.f, 0.f);
            uint32_t h0, l0, h1, l1;
            split_pair(v.x, v.y, h0, l0);
            split_pair(v.z, v.w, h1, l1);
            uint32_t off = r * ROWB1 + c4 * 8;
            *(uint2*)(pAh + off) = make_uint2(h0, h1);
            *(uint2*)(pAl + off) = make_uint2(l0, l1);
        }
        // copy pre-split W tiles: 1024 uint4 / 256 thr = 4 each
#pragma unroll
        for (int i = tid; i < 1024; i += 256) {
            int r = i >> 3, c4 = i & 7;
            *(uint4*)(pWh + r * ROWB1 + c4 * 16) = *(const uint4*)(g_W1h + (size_t)r * DIN + k0 + c4 * 8);
            *(uint4*)(pWl + r * ROWB1 + c4 * 16) = *(const uint4*)(g_W1l + (size_t)r * DIN + k0 + c4 * 8);
        }
        __syncthreads();

#pragma unroll
        for (int s = 0; s < KC1 / 16; s++) {
            const int kc = s * 16;
            uint32_t afh[4][4], afl[4][4], bfh[4][2], bfl[4][2];
#pragma unroll
            for (int m = 0; m < 4; m++) {
                uint32_t off = (uint32_t)(wm * 64 + m * 16 + (lane & 15)) * ROWB1
                             + (kc + (lane >> 4) * 8) * 2;
                ldsm4(afh[m], sAh + off);
                ldsm4(afl[m], sAl + off);
            }
#pragma unroll
            for (int p = 0; p < 2; p++) {
                uint32_t off = (uint32_t)(wn * 32 + p * 16 + ((lane >> 4) & 1) * 8 + (lane & 7)) * ROWB1
                             + (kc + ((lane >> 3) & 1) * 8) * 2;
                ldsm4(&bfh[p * 2][0], sWh + off);
                ldsm4(&bfl[p * 2][0], sWl + off);
            }
#pragma unroll
            for (int m = 0; m < 4; m++)
#pragma unroll
                for (int q = 0; q < 4; q++) {
                    mma_bf16(acc[m][q], afh[m], bfh[q]);
                    mma_bf16(acc[m][q], afh[m], bfl[q]);
                    mma_bf16(acc[m][q], afl[m], bfh[q]);
                }
        }
    }

    // ---- epilogue: store ft1 + fused el/er ----
    const int qr = lane >> 2, qc = lane & 3;
    float av[4][2], bv[4][2];
#pragma unroll
    for (int q = 0; q < 4; q++) {
        int cc = wn * 32 + q * 8 + qc * 2;
        av[q][0] = __ldg(al1 + cc); av[q][1] = __ldg(al1 + cc + 1);
        bv[q][0] = __ldg(ar1 + cc); bv[q][1] = __ldg(ar1 + cc + 1);
    }
    float elp[4][2][2], erp[4][2][2];
#pragma unroll
    for (int m = 0; m < 4; m++)
#pragma unroll
        for (int hh = 0; hh < 2; hh++) {
            elp[m][hh][0] = 0.f; elp[m][hh][1] = 0.f;
            erp[m][hh][0] = 0.f; erp[m][hh][1] = 0.f;
        }

#pragma unroll
    for (int m = 0; m < 4; m++) {
        int ra = row0 + wm * 64 + m * 16 + qr;
        int rb = ra + 8;
#pragma unroll
        for (int q = 0; q < 4; q++) {
            int cc = wn * 32 + q * 8 + qc * 2;
            float d0 = acc[m][q][0], d1 = acc[m][q][1];
            float d2 = acc[m][q][2], d3 = acc[m][q][3];
            if (ra < n) *(float2*)(g_ft1 + (size_t)ra * C1 + cc) = make_float2(d0, d1);
            if (rb < n) *(float2*)(g_ft1 + (size_t)rb * C1 + cc) = make_float2(d2, d3);
            int hl = q >> 1;
            elp[m][0][hl] += d0 * av[q][0] + d1 * av[q][1];
            elp[m][1][hl] += d2 * av[q][0] + d3 * av[q][1];
            erp[m][0][hl] += d0 * bv[q][0] + d1 * bv[q][1];
            erp[m][1][hl] += d2 * bv[q][0] + d3 * bv[q][1];
        }
    }
#pragma unroll
    for (int off = 1; off <= 2; off <<= 1) {
#pragma unroll
        for (int m = 0; m < 4; m++)
#pragma unroll
            for (int hh = 0; hh < 2; hh++)
#pragma unroll
                for (int hl = 0; hl < 2; hl++) {
                    elp[m][hh][hl] += __shfl_xor_sync(0xffffffffu, elp[m][hh][hl], off);
                    erp[m][hh][hl] += __shfl_xor_sync(0xffffffffu, erp[m][hh][hl], off);
                }
    }
    if (qc == 0) {
        int h0 = wn * 2;
#pragma unroll
        for (int m = 0; m < 4; m++) {
            int ra = row0 + wm * 64 + m * 16 + qr;
            int rb = ra + 8;
            if (ra < n) {
                *(float2*)(g_el1 + ra * H1h + h0) = make_float2(elp[m][0][0], elp[m][0][1]);
                *(float2*)(g_er1 + ra * H1h + h0) = make_float2(erp[m][0][0], erp[m][0][1]);
            }
            if (rb < n) {
                *(float2*)(g_el1 + rb * H1h + h0) = make_float2(elp[m][1][0], elp[m][1][1]);
                *(float2*)(g_er1 + rb * H1h + h0) = make_float2(erp[m][1][0], erp[m][1][1]);
            }
        }
    }
}

// ================= tensor-core GEMM2 via mma.sync (split-bf16) =================
#define KC2 32
#define NCH2 (C1 / KC2)   // 4 chunks
#define LDE    40
#define ROWB   (LDE * 2)

__global__ void __launch_bounds__(256) gemm2_mma_kernel(
    const float* __restrict__ A,
    const float* __restrict__ al2, const float* __restrict__ ar2, int n)
{
    __shared__ __align__(16) char sm[(2 * 128 + 2 * 64) * ROWB];   // 30 KB
    const uint32_t sAh = smem_u32(sm);
    const uint32_t sAl = sAh + 128 * ROWB;
    const uint32_t sWh = sAl + 128 * ROWB;
    const uint32_t sWl = sWh + 64 * ROWB;
    char* pAh = sm;
    char* pAl = sm + 128 * ROWB;
    char* pWh = sm + 2 * 128 * ROWB;
    char* pWl = sm + (2 * 128 + 64) * ROWB;

    const int tid = threadIdx.x;
    const int lane = tid & 31, wid = tid >> 5;
    const int wm = wid >> 2, wn = wid & 3;   // 2 x 4; warp tile 64 x 16
    const int row0 = blockIdx.x * 128;

    float acc[4][2][4];
#pragma unroll
    for (int m = 0; m < 4; m++)
#pragma unroll
        for (int q = 0; q < 2; q++)
#pragma unroll
            for (int r = 0; r < 4; r++) acc[m][q][r] = 0.f;

    for (int c = 0; c < NCH2; c++) {
        const int k0 = c * KC2;
        __syncthreads();
#pragma unroll
        for (int i = tid; i < 1024; i += 256) {
            int r = i >> 3, c4 = i & 7;
            int row = row0 + r;
            float4 v = (row < n) ? *(const float4*)(A + (size_t)row * C1 + k0 + c4 * 4)
                                 : make_float4(0.f, 0.f, 0.f, 0.f);
            uint32_t h0, l0, h1, l1;
            split_pair(v.x, v.y, h0, l0);
            split_pair(v.z, v.w, h1, l1);
            uint32_t off = r * ROWB + c4 * 8;
            *(uint2*)(pAh + off) = make_uint2(h0, h1);
            *(uint2*)(pAl + off) = make_uint2(l0, l1);
        }
#pragma unroll
        for (int i = tid; i < 256; i += 256) {
            int r = i >> 2, c4 = i & 3;
            *(uint4*)(pWh + r * ROWB + c4 * 16) = *(const uint4*)(g_W2h + (size_t)r * C1 + k0 + c4 * 8);
            *(uint4*)(pWl + r * ROWB + c4 * 16) = *(const uint4*)(g_W2l + (size_t)r * C1 + k0 + c4 * 8);
        }
        __syncthreads();

#pragma unroll
        for (int s = 0; s < KC2 / 16; s++) {
            const int kc = s * 16;
            uint32_t afh[4][4], afl[4][4], bfh[2][2], bfl[2][2];
#pragma unroll
            for (int m = 0; m < 4; m++) {
                uint32_t off = (uint32_t)(wm * 64 + m * 16 + (lane & 15)) * ROWB
                             + (kc + (lane >> 4) * 8) * 2;
                ldsm4(afh[m], sAh + off);
                ldsm4(afl[m], sAl + off);
            }
            {
                uint32_t off = (uint32_t)(wn * 16 + ((lane >> 4) & 1) * 8 + (lane & 7)) * ROWB
                             + (kc + ((lane >> 3) & 1) * 8) * 2;
                ldsm4(&bfh[0][0], sWh + off);
                ldsm4(&bfl[0][0], sWl + off);
            }
#pragma unroll
            for (int m = 0; m < 4; m++)
#pragma unroll
                for (int q = 0; q < 2; q++) {
                    mma_bf16(acc[m][q], afh[m], bfh[q]);
                    mma_bf16(acc[m][q], afh[m], bfl[q]);
                    mma_bf16(acc[m][q], afl[m], bfh[q]);
                }
        }
    }

    // ---- epilogue: store ft2 + fused el2/er2 partials ----
    const int qr = lane >> 2, qc = lane & 3;
    float av2[2][2], bv2[2][2];
#pragma unroll
    for (int q = 0; q < 2; q++) {
        int cc = wn * 16 + q * 8 + qc * 2;
        av2[q][0] = __ldg(al2 + cc); av2[q][1] = __ldg(al2 + cc + 1);
        bv2[q][0] = __ldg(ar2 + cc); bv2[q][1] = __ldg(ar2 + cc + 1);
    }
    float elp[4][2], erp[4][2];
#pragma unroll
    for (int m = 0; m < 4; m++) {
        elp[m][0] = 0.f; elp[m][1] = 0.f;
        erp[m][0] = 0.f; erp[m][1] = 0.f;
    }
#pragma unroll
    for (int m = 0; m < 4; m++) {
        int ra = row0 + wm * 64 + m * 16 + qr;
        int rb = ra + 8;
#pragma unroll
        for (int q = 0; q < 2; q++) {
            int cc = wn * 16 + q * 8 + qc * 2;
            float d0 = acc[m][q][0], d1 = acc[m][q][1];
            float d2 = acc[m][q][2], d3 = acc[m][q][3];
            if (ra < n) *(float2*)(g_ft2 + (size_t)ra * D2 + cc) = make_float2(d0, d1);
            if (rb < n) *(float2*)(g_ft2 + (size_t)rb * D2 + cc) = make_float2(d2, d3);
            elp[m][0] += d0 * av2[q][0] + d1 * av2[q][1];
            elp[m][1] += d2 * av2[q][0] + d3 * av2[q][1];
            erp[m][0] += d0 * bv2[q][0] + d1 * bv2[q][1];
            erp[m][1] += d2 * bv2[q][0] + d3 * bv2[q][1];
        }
    }
#pragma unroll
    for (int off = 1; off <= 2; off <<= 1) {
#pragma unroll
        for (int m = 0; m < 4; m++)
#pragma unroll
            for (int hh = 0; hh < 2; hh++) {
                elp[m][hh] += __shfl_xor_sync(0xffffffffu, elp[m][hh], off);
                erp[m][hh] += __shfl_xor_sync(0xffffffffu, erp[m][hh], off);
            }
    }
    if (qc == 0) {
#pragma unroll
        for (int m = 0; m < 4; m++) {
            int ra = row0 + wm * 64 + m * 16 + qr;
            int rb = ra + 8;
            if (ra < n) { atomicAdd(&g_el2[ra], elp[m][0]); atomicAdd(&g_er2[ra], erp[m][0]); }
            if (rb < n) { atomicAdd(&g_el2[rb], elp[m][1]); atomicAdd(&g_er2[rb], erp[m][1]); }
        }
    }
}

// ================= fused GAT aggregation (batched-index edge loops) =============
__global__ void __launch_bounds__(256) gat1_acc_kernel(float* __restrict__ out_h1, int n) {
    int node = (blockIdx.x * blockDim.x + threadIdx.x) >> 5;
    int lane = threadIdx.x & 31;
    if (node >= n) return;
    const int row0 = g_rowstart[node];
    const int deg  = g_hist[node];
    const int h = lane >> 2;
    float er = (lane < H1h) ? g_er1[node * H1h + lane] : 0.f;

    float ssum = 0.f;
    float a0 = 0.f, a1 = 0.f, a2 = 0.f, a3 = 0.f;

    for (int k0 = 0; k0 < deg; k0 += 32) {
        const int rem = deg - k0;
        const int nb = rem < 32 ? rem : 32;
        int sidx = 0;
        if (lane < rem) sidx = __ldg(&g_ssrc[row0 + k0 + lane]);
#pragma unroll 4
        for (int j = 0; j < nb; j++) {
            int s = __shfl_sync(0xffffffffu, sidx, j);
            float4 f = *(const float4*)(g_ft1 + (size_t)s * C1 + lane * 4);
            float ex = 0.f;
            if (lane < H1h) {
                float v = g_el1[s * H1h + lane] + er;
                v = (v >= 0.f) ? v : SLOPE * v;
                ex = __expf(v);
                ssum += ex;
            }
            float exl = __shfl_sync(0xffffffffu, ex, h);
            a0 = fmaf(f.x, exl, a0);
            a1 = fmaf(f.y, exl, a1);
            a2 = fmaf(f.z, exl, a2);
            a3 = fmaf(f.w, exl, a3);
        }
    }
    float ssl = __shfl_sync(0xffffffffu, ssum, h);
    float inv = (ssl > 0.f) ? 1.f / ssl : 0.f;
    float4 o;
    o.x = fmaxf(a0 * inv, 0.f);
    o.y = fmaxf(a1 * inv, 0.f);
    o.z = fmaxf(a2 * inv, 0.f);
    o.w = fmaxf(a3 * inv, 0.f);
    *(float4*)(out_h1 + (size_t)node * C1 + lane * 4) = o;
}

__global__ void __launch_bounds__(256) gat2_acc_kernel(float* __restrict__ out_h, int n) {
    int node = (blockIdx.x * blockDim.x + threadIdx.x) >> 5;
    int lane = threadIdx.x & 31;
    if (node >= n) return;
    const int row0 = g_rowstart[node];
    const int deg  = g_hist[node];
    const float er = g_er2[node];

    float ssum = 0.f;
    float a0 = 0.f, a1 = 0.f;

    for (int k0 = 0; k0 < deg; k0 += 32) {
        const int rem = deg - k0;
        const int nb = rem < 32 ? rem : 32;
        int sidx = 0;
        float exv = 0.f;
        if (lane < rem) {
            sidx = __ldg(&g_ssrc[row0 + k0 + lane]);
            float v = g_el2[sidx] + er;      // lane-parallel exp precompute
            v = (v >= 0.f) ? v : SLOPE * v;
            exv = __expf(v);
            ssum += exv;
        }
#pragma unroll 4
        for (int j = 0; j < nb; j++) {
            int s = __shfl_sync(0xffffffffu, sidx, j);
            float exl = __shfl_sync(0xffffffffu, exv, j);
            float2 f = *(const float2*)(g_ft2 + (size_t)s * D2 + lane * 2);
            a0 = fmaf(f.x, exl, a0);
            a1 = fmaf(f.y, exl, a1);
        }
    }
#pragma unroll
    for (int off = 16; off >= 1; off >>= 1)
        ssum += __shfl_xor_sync(0xffffffffu, ssum, off);
    float inv = (ssum > 0.f) ? 1.f / ssum : 0.f;
    float2 o;
    o.x = a0 * inv;
    o.y = a1 * inv;
    *(float2*)(out_h + (size_t)node * D2 + lane * 2) = o;
}

// ================= launch =================
extern "C" void kernel_launch(void* const* d_in, const int* in_sizes, int n_in,
                              void* d_out, int out_size) {
    const float* feats = (const float*)d_in[0];
    const int*   src   = (const int*)d_in[1];
    const int*   dst   = (const int*)d_in[2];
    const float* W1    = (const float*)d_in[3];
    const float* al1   = (const float*)d_in[4];
    const float* ar1   = (const float*)d_in[5];
    const float* W2    = (const float*)d_in[6];
    const float* al2   = (const float*)d_in[7];
    const float* ar2   = (const float*)d_in[8];
    float* out = (float*)d_out;

    const int n = in_sizes[0] / DIN;   // 100000
    const int E = in_sizes[1];         // 1600000

    float* out_h1 = out + (size_t)n * DIN;
    float* out_h  = out_h1 + (size_t)n * C1;

    cudaFuncSetAttribute(gemm1_mma_kernel,
                         cudaFuncAttributeMaxDynamicSharedMemorySize, G1_SMEM);

    // ---- fork a side stream: CSR build, then off-critical-path memcpy ----
    cudaStream_t s1;
    cudaEvent_t evFork, evJoin, evCopyDone;
    cudaStreamCreateWithFlags(&s1, cudaStreamNonBlocking);
    cudaEventCreateWithFlags(&evFork, cudaEventDisableTiming);
    cudaEventCreateWithFlags(&evJoin, cudaEventDisableTiming);
    cudaEventCreateWithFlags(&evCopyDone, cudaEventDisableTiming);

    cudaEventRecord(evFork, 0);
    cudaStreamWaitEvent(s1, evFork, 0);

    // side branch: dst-CSR counting sort (+ el2/er2 zero)
    const int nb = (n + SCAN_B - 1) / SCAN_B;
    zero_hist<<<(n + 255) / 256, 256, 0, s1>>>(n);
    hist_kernel<<<(E + 255) / 256, 256, 0, s1>>>(dst, E);
    scanA<<<nb, SCAN_B, 0, s1>>>(n);
    scanB<<<1, 128, 0, s1>>>(nb);
    scanC<<<(n + 255) / 256, 256, 0, s1>>>(n);
    scatter_kernel<<<(E + 255) / 256, 256, 0, s1>>>(src, dst, E);
    cudaEventRecord(evJoin, s1);

    // feats -> out copy: no dependents; overlaps gat/gemm phase; joined at end.
    cudaMemcpyAsync(out, feats, (size_t)n * DIN * sizeof(float),
                    cudaMemcpyDeviceToDevice, s1);
    cudaEventRecord(evCopyDone, s1);

    // main branch: weight split + layer-1 GEMM (+ fused coef1 epilogue)
    splitW_kernel<<<(C1 * DIN + D2 * C1 + 255) / 256, 256>>>(W1, W2);
    gemm1_mma_kernel<<<(n + 127) / 128, 256, G1_SMEM>>>(feats, al1, ar1, n);

    // join: aggregation needs the CSR
    cudaStreamWaitEvent(0, evJoin, 0);
    gat1_acc_kernel<<<(n * 32 + 255) / 256, 256>>>(out_h1, n);

    // ---- layer 2 (coef2 fused into gemm2 epilogue) ----
    gemm2_mma_kernel<<<(n + 127) / 128, 256>>>(out_h1, al2, ar2, n);
    gat2_acc_kernel<<<(n * 32 + 255) / 256, 256>>>(out_h, n);

    // final join of the copy branch (keeps graph capture fully joined)
    cudaStreamWaitEvent(0, evCopyDone, 0);
}

// round 16
// speedup vs baseline: 1.0262x; 1.0262x over previous
#include <cuda_runtime.h>
#include <cuda_bf16.h>
#include <cstdint>

#define Nn   100000
#define Emax 1600000
#define DIN  512
#define H1h  8
#define C1   128   // H1*D1
#define D2   64
#define SLOPE 0.2f
#define SCAN_B 1024

// ---------------- scratch (device globals; no allocs allowed) ----------------
__device__ float g_ft1[(size_t)Nn * C1];
__device__ float g_el1[Nn * H1h];
__device__ float g_er1[Nn * H1h];
__device__ float g_ft2[(size_t)Nn * D2];
__device__ float g_el2[Nn];
__device__ float g_er2[Nn];

__device__ __nv_bfloat16 g_W1h[C1 * DIN];
__device__ __nv_bfloat16 g_W1l[C1 * DIN];
__device__ __nv_bfloat16 g_W2h[D2 * C1];
__device__ __nv_bfloat16 g_W2l[D2 * C1];

__device__ int g_hist[Nn];
__device__ int g_scan[Nn];
__device__ int g_bsum[128];
__device__ int g_boff[128];
__device__ int g_rowstart[Nn];
__device__ int g_cursor[Nn];
__device__ int g_ssrc[Emax];

// ================= helpers =================
__device__ __forceinline__ uint32_t smem_u32(const void* p) {
    uint32_t a;
    asm("{ .reg .u64 t; cvta.to.shared.u64 t, %1; cvt.u32.u64 %0, t; }" : "=r"(a) : "l"(p));
    return a;
}
__device__ __forceinline__ void ldsm4(uint32_t* r, uint32_t addr) {
    asm volatile("ldmatrix.sync.aligned.m8n8.x4.shared.b16 {%0,%1,%2,%3}, [%4];"
        : "=r"(r[0]), "=r"(r[1]), "=r"(r[2]), "=r"(r[3]) : "r"(addr));
}
__device__ __forceinline__ void mma_bf16(float* d, const uint32_t* a, const uint32_t* b) {
    asm volatile("mma.sync.aligned.m16n8k16.row.col.f32.bf16.bf16.f32 "
        "{%0,%1,%2,%3}, {%4,%5,%6,%7}, {%8,%9}, {%0,%1,%2,%3};"
        : "+f"(d[0]), "+f"(d[1]), "+f"(d[2]), "+f"(d[3])
        : "r"(a[0]), "r"(a[1]), "r"(a[2]), "r"(a[3]), "r"(b[0]), "r"(b[1]));
}
__device__ __forceinline__ void split_pair(float x, float y, uint32_t& hi, uint32_t& lo) {
    __nv_bfloat16 hx = __float2bfloat16(x), hy = __float2bfloat16(y);
    __nv_bfloat16 lx = __float2bfloat16(x - __bfloat162float(hx));
    __nv_bfloat16 ly = __float2bfloat16(y - __bfloat162float(hy));
    __nv_bfloat162 h(hx, hy), l(lx, ly);
    hi = *(uint32_t*)&h;
    lo = *(uint32_t*)&l;
}

// ================= pre-split weights =================
__global__ void splitW_kernel(const float* __restrict__ W1, const float* __restrict__ W2) {
    int i = blockIdx.x * blockDim.x + threadIdx.x;
    if (i < C1 * DIN) {
        float v = W1[i];
        __nv_bfloat16 h = __float2bfloat16(v);
        g_W1h[i] = h;
        g_W1l[i] = __float2bfloat16(v - __bfloat162float(h));
    }
    int j = i - C1 * DIN;
    if (j >= 0 && j < D2 * C1) {
        float v = W2[j];
        __nv_bfloat16 h = __float2bfloat16(v);
        g_W2h[j] = h;
        g_W2l[j] = __float2bfloat16(v - __bfloat162float(h));
    }
}

// ================= counting sort by dst (+ zero el2/er2 for gemm2 atomics) =====
__global__ void zero_hist(int n) {
    int i = blockIdx.x * blockDim.x + threadIdx.x;
    if (i < n) { g_hist[i] = 0; g_el2[i] = 0.f; g_er2[i] = 0.f; }
}
__global__ void hist_kernel(const int* __restrict__ dst, int E) {
    int e = blockIdx.x * blockDim.x + threadIdx.x;
    if (e < E) atomicAdd(&g_hist[dst[e]], 1);
}
__global__ void scanA(int n) {
    __shared__ int sm[SCAN_B];
    int idx = blockIdx.x * SCAN_B + threadIdx.x;
    int v = (idx < n) ? g_hist[idx] : 0;
    sm[threadIdx.x] = v;
    __syncthreads();
#pragma unroll
    for (int off = 1; off < SCAN_B; off <<= 1) {
        int t = (threadIdx.x >= off) ? sm[threadIdx.x - off] : 0;
        __syncthreads();
        sm[threadIdx.x] += t;
        __syncthreads();
    }
    if (idx < n) g_scan[idx] = sm[threadIdx.x];
    if (threadIdx.x == SCAN_B - 1) g_bsum[blockIdx.x] = sm[threadIdx.x];
}
__global__ void scanB(int nb) {
    __shared__ int sm[128];
    int v = (threadIdx.x < nb) ? g_bsum[threadIdx.x] : 0;
    sm[threadIdx.x] = v;
    __syncthreads();
#pragma unroll
    for (int off = 1; off < 128; off <<= 1) {
        int t = (threadIdx.x >= off) ? sm[threadIdx.x - off] : 0;
        __syncthreads();
        sm[threadIdx.x] += t;
        __syncthreads();
    }
    if (threadIdx.x < nb) g_boff[threadIdx.x] = sm[threadIdx.x] - v;
}
__global__ void scanC(int n) {
    int idx = blockIdx.x * blockDim.x + threadIdx.x;
    if (idx < n) {
        int ex = g_scan[idx] - g_hist[idx] + g_boff[idx >> 10];
        g_rowstart[idx] = ex;
        g_cursor[idx]   = ex;
    }
}
__global__ void scatter_kernel(const int* __restrict__ src, const int* __restrict__ dst, int E) {
    int e = blockIdx.x * blockDim.x + threadIdx.x;
    if (e < E) {
        int d = dst[e];
        int pos = atomicAdd(&g_cursor[d], 1);
        g_ssrc[pos] = src[e];
    }
}

// ================= tensor-core GEMM1 via mma.sync (split-bf16) =================
// Round-14 best config: 256 threads / 8 warps, 2x4 grid, warp tile 64x32,
// KC1=64, 72KB dynamic SMEM, no min-blocks clamp (the (256,2) variant
// regressed +5us from register squeeze).
#define KC1    64
#define NCH1   (DIN / KC1)     // 8 chunks
#define LDE1   72              // padded row stride in bf16 elems (144 B)
#define ROWB1  (LDE1 * 2)
#define G1_SMEM (4 * 128 * ROWB1)   // 73728 B

__global__ void __launch_bounds__(256) gemm1_mma_kernel(
    const float* __restrict__ A,
    const float* __restrict__ al1, const float* __restrict__ ar1, int n)
{
    extern __shared__ __align__(16) char sm1[];
    const uint32_t sAh = smem_u32(sm1);
    const uint32_t sAl = sAh + 128 * ROWB1;
    const uint32_t sWh = sAl + 128 * ROWB1;
    const uint32_t sWl = sWh + 128 * ROWB1;
    char* pAh = sm1;
    char* pAl = sm1 + 128 * ROWB1;
    char* pWh = sm1 + 2 * 128 * ROWB1;
    char* pWl = sm1 + 3 * 128 * ROWB1;

    const int tid = threadIdx.x;
    const int lane = tid & 31, wid = tid >> 5;
    const int wm = wid >> 2, wn = wid & 3;         // 2 x 4 warp grid
    const int row0 = blockIdx.x * 128;

    float acc[4][4][4];
#pragma unroll
    for (int m = 0; m < 4; m++)
#pragma unroll
        for (int q = 0; q < 4; q++)
#pragma unroll
            for (int r = 0; r < 4; r++) acc[m][q][r] = 0.f;

    for (int c = 0; c < NCH1; c++) {
        const int k0 = c * KC1;
        __syncthreads();
        // load + split A: 2048 float4 / 256 thr = 8 each; uint2 (STS.64) stores
#pragma unroll
        for (int i = tid; i < 2048; i += 256) {
            int r = i >> 4, c4 = i & 15;
            int row = row0 + r;
            float4 v = (row < n) ? *(const float4*)(A + (size_t)row * DIN + k0 + c4 * 4)
                                 : make_float4(0.f, 0.f, 0.f, 0.f);
            uint32_t h0, l0, h1, l1;
            split_pair(v.x, v.y, h0, l0);
            split_pair(v.z, v.w, h1, l1);
            uint32_t off = r * ROWB1 + c4 * 8;
            *(uint2*)(pAh + off) = make_uint2(h0, h1);
            *(uint2*)(pAl + off) = make_uint2(l0, l1);
        }
        // copy pre-split W tiles: 1024 uint4 / 256 thr = 4 each
#pragma unroll
        for (int i = tid; i < 1024; i += 256) {
            int r = i >> 3, c4 = i & 7;
            *(uint4*)(pWh + r * ROWB1 + c4 * 16) = *(const uint4*)(g_W1h + (size_t)r * DIN + k0 + c4 * 8);
            *(uint4*)(pWl + r * ROWB1 + c4 * 16) = *(const uint4*)(g_W1l + (size_t)r * DIN + k0 + c4 * 8);
        }
        __syncthreads();

#pragma unroll
        for (int s = 0; s < KC1 / 16; s++) {
            const int kc = s * 16;
            uint32_t afh[4][4], afl[4][4], bfh[4][2], bfl[4][2];
#pragma unroll
            for (int m = 0; m < 4; m++) {
                uint32_t off = (uint32_t)(wm * 64 + m * 16 + (lane & 15)) * ROWB1
                             + (kc + (lane >> 4) * 8) * 2;
                ldsm4(afh[m], sAh + off);
                ldsm4(afl[m], sAl + off);
            }
#pragma unroll
            for (int p = 0; p < 2; p++) {
                uint32_t off = (uint32_t)(wn * 32 + p * 16 + ((lane >> 4) & 1) * 8 + (lane & 7)) * ROWB1
                             + (kc + ((lane >> 3) & 1) * 8) * 2;
                ldsm4(&bfh[p * 2][0], sWh + off);
                ldsm4(&bfl[p * 2][0], sWl + off);
            }
#pragma unroll
            for (int m = 0; m < 4; m++)
#pragma unroll
                for (int q = 0; q < 4; q++) {
                    mma_bf16(acc[m][q], afh[m], bfh[q]);
                    mma_bf16(acc[m][q], afh[m], bfl[q]);
                    mma_bf16(acc[m][q], afl[m], bfh[q]);
                }
        }
    }

    // ---- epilogue: store ft1 + fused el/er ----
    const int qr = lane >> 2, qc = lane & 3;
    float av[4][2], bv[4][2];
#pragma unroll
    for (int q = 0; q < 4; q++) {
        int cc = wn * 32 + q * 8 + qc * 2;
        av[q][0] = __ldg(al1 + cc); av[q][1] = __ldg(al1 + cc + 1);
        bv[q][0] = __ldg(ar1 + cc); bv[q][1] = __ldg(ar1 + cc + 1);
    }
    float elp[4][2][2], erp[4][2][2];
#pragma unroll
    for (int m = 0; m < 4; m++)
#pragma unroll
        for (int hh = 0; hh < 2; hh++) {
            elp[m][hh][0] = 0.f; elp[m][hh][1] = 0.f;
            erp[m][hh][0] = 0.f; erp[m][hh][1] = 0.f;
        }

#pragma unroll
    for (int m = 0; m < 4; m++) {
        int ra = row0 + wm * 64 + m * 16 + qr;
        int rb = ra + 8;
#pragma unroll
        for (int q = 0; q < 4; q++) {
            int cc = wn * 32 + q * 8 + qc * 2;
            float d0 = acc[m][q][0], d1 = acc[m][q][1];
            float d2 = acc[m][q][2], d3 = acc[m][q][3];
            if (ra < n) *(float2*)(g_ft1 + (size_t)ra * C1 + cc) = make_float2(d0, d1);
            if (rb < n) *(float2*)(g_ft1 + (size_t)rb * C1 + cc) = make_float2(d2, d3);
            int hl = q >> 1;
            elp[m][0][hl] += d0 * av[q][0] + d1 * av[q][1];
            elp[m][1][hl] += d2 * av[q][0] + d3 * av[q][1];
            erp[m][0][hl] += d0 * bv[q][0] + d1 * bv[q][1];
            erp[m][1][hl] += d2 * bv[q][0] + d3 * bv[q][1];
        }
    }
#pragma unroll
    for (int off = 1; off <= 2; off <<= 1) {
#pragma unroll
        for (int m = 0; m < 4; m++)
#pragma unroll
            for (int hh = 0; hh < 2; hh++)
#pragma unroll
                for (int hl = 0; hl < 2; hl++) {
                    elp[m][hh][hl] += __shfl_xor_sync(0xffffffffu, elp[m][hh][hl], off);
                    erp[m][hh][hl] += __shfl_xor_sync(0xffffffffu, erp[m][hh][hl], off);
                }
    }
    if (qc == 0) {
        int h0 = wn * 2;
#pragma unroll
        for (int m = 0; m < 4; m++) {
            int ra = row0 + wm * 64 + m * 16 + qr;
            int rb = ra + 8;
            if (ra < n) {
                *(float2*)(g_el1 + ra * H1h + h0) = make_float2(elp[m][0][0], elp[m][0][1]);
                *(float2*)(g_er1 + ra * H1h + h0) = make_float2(erp[m][0][0], erp[m][0][1]);
            }
            if (rb < n) {
                *(float2*)(g_el1 + rb * H1h + h0) = make_float2(elp[m][1][0], elp[m][1][1]);
                *(float2*)(g_er1 + rb * H1h + h0) = make_float2(erp[m][1][0], erp[m][1][1]);
            }
        }
    }
}

// ================= tensor-core GEMM2 via mma.sync (split-bf16) =================
#define KC2 32
#define NCH2 (C1 / KC2)   // 4 chunks
#define LDE    40
#define ROWB   (LDE * 2)

__global__ void __launch_bounds__(256) gemm2_mma_kernel(
    const float* __restrict__ A,
    const float* __restrict__ al2, const float* __restrict__ ar2, int n)
{
    __shared__ __align__(16) char sm[(2 * 128 + 2 * 64) * ROWB];   // 30 KB
    const uint32_t sAh = smem_u32(sm);
    const uint32_t sAl = sAh + 128 * ROWB;
    const uint32_t sWh = sAl + 128 * ROWB;
    const uint32_t sWl = sWh + 64 * ROWB;
    char* pAh = sm;
    char* pAl = sm + 128 * ROWB;
    char* pWh = sm + 2 * 128 * ROWB;
    char* pWl = sm + (2 * 128 + 64) * ROWB;

    const int tid = threadIdx.x;
    const int lane = tid & 31, wid = tid >> 5;
    const int wm = wid >> 2, wn = wid & 3;   // 2 x 4; warp tile 64 x 16
    const int row0 = blockIdx.x * 128;

    float acc[4][2][4];
#pragma unroll
    for (int m = 0; m < 4; m++)
#pragma unroll
        for (int q = 0; q < 2; q++)
#pragma unroll
            for (int r = 0; r < 4; r++) acc[m][q][r] = 0.f;

    for (int c = 0; c < NCH2; c++) {
        const int k0 = c * KC2;
        __syncthreads();
#pragma unroll
        for (int i = tid; i < 1024; i += 256) {
            int r = i >> 3, c4 = i & 7;
            int row = row0 + r;
            float4 v = (row < n) ? *(const float4*)(A + (size_t)row * C1 + k0 + c4 * 4)
                                 : make_float4(0.f, 0.f, 0.f, 0.f);
            uint32_t h0, l0, h1, l1;
            split_pair(v.x, v.y, h0, l0);
            split_pair(v.z, v.w, h1, l1);
            uint32_t off = r * ROWB + c4 * 8;
            *(uint2*)(pAh + off) = make_uint2(h0, h1);
            *(uint2*)(pAl + off) = make_uint2(l0, l1);
        }
#pragma unroll
        for (int i = tid; i < 256; i += 256) {
            int r = i >> 2, c4 = i & 3;
            *(uint4*)(pWh + r * ROWB + c4 * 16) = *(const uint4*)(g_W2h + (size_t)r * C1 + k0 + c4 * 8);
            *(uint4*)(pWl + r * ROWB + c4 * 16) = *(const uint4*)(g_W2l + (size_t)r * C1 + k0 + c4 * 8);
        }
        __syncthreads();

#pragma unroll
        for (int s = 0; s < KC2 / 16; s++) {
            const int kc = s * 16;
            uint32_t afh[4][4], afl[4][4], bfh[2][2], bfl[2][2];
#pragma unroll
            for (int m = 0; m < 4; m++) {
                uint32_t off = (uint32_t)(wm * 64 + m * 16 + (lane & 15)) * ROWB
                             + (kc + (lane >> 4) * 8) * 2;
                ldsm4(afh[m], sAh + off);
                ldsm4(afl[m], sAl + off);
            }
            {
                uint32_t off = (uint32_t)(wn * 16 + ((lane >> 4) & 1) * 8 + (lane & 7)) * ROWB
                             + (kc + ((lane >> 3) & 1) * 8) * 2;
                ldsm4(&bfh[0][0], sWh + off);
                ldsm4(&bfl[0][0], sWl + off);
            }
#pragma unroll
            for (int m = 0; m < 4; m++)
#pragma unroll
                for (int q = 0; q < 2; q++) {
                    mma_bf16(acc[m][q], afh[m], bfh[q]);
                    mma_bf16(acc[m][q], afh[m], bfl[q]);
                    mma_bf16(acc[m][q], afl[m], bfh[q]);
                }
        }
    }

    // ---- epilogue: store ft2 + fused el2/er2 partials ----
    const int qr = lane >> 2, qc = lane & 3;
    float av2[2][2], bv2[2][2];
#pragma unroll
    for (int q = 0; q < 2; q++) {
        int cc = wn * 16 + q * 8 + qc * 2;
        av2[q][0] = __ldg(al2 + cc); av2[q][1] = __ldg(al2 + cc + 1);
        bv2[q][0] = __ldg(ar2 + cc); bv2[q][1] = __ldg(ar2 + cc + 1);
    }
    float elp[4][2], erp[4][2];
#pragma unroll
    for (int m = 0; m < 4; m++) {
        elp[m][0] = 0.f; elp[m][1] = 0.f;
        erp[m][0] = 0.f; erp[m][1] = 0.f;
    }
#pragma unroll
    for (int m = 0; m < 4; m++) {
        int ra = row0 + wm * 64 + m * 16 + qr;
        int rb = ra + 8;
#pragma unroll
        for (int q = 0; q < 2; q++) {
            int cc = wn * 16 + q * 8 + qc * 2;
            float d0 = acc[m][q][0], d1 = acc[m][q][1];
            float d2 = acc[m][q][2], d3 = acc[m][q][3];
            if (ra < n) *(float2*)(g_ft2 + (size_t)ra * D2 + cc) = make_float2(d0, d1);
            if (rb < n) *(float2*)(g_ft2 + (size_t)rb * D2 + cc) = make_float2(d2, d3);
            elp[m][0] += d0 * av2[q][0] + d1 * av2[q][1];
            elp[m][1] += d2 * av2[q][0] + d3 * av2[q][1];
            erp[m][0] += d0 * bv2[q][0] + d1 * bv2[q][1];
            erp[m][1] += d2 * bv2[q][0] + d3 * bv2[q][1];
        }
    }
#pragma unroll
    for (int off = 1; off <= 2; off <<= 1) {
#pragma unroll
        for (int m = 0; m < 4; m++)
#pragma unroll
            for (int hh = 0; hh < 2; hh++) {
                elp[m][hh] += __shfl_xor_sync(0xffffffffu, elp[m][hh], off);
                erp[m][hh] += __shfl_xor_sync(0xffffffffu, erp[m][hh], off);
            }
    }
    if (qc == 0) {
#pragma unroll
        for (int m = 0; m < 4; m++) {
            int ra = row0 + wm * 64 + m * 16 + qr;
            int rb = ra + 8;
            if (ra < n) { atomicAdd(&g_el2[ra], elp[m][0]); atomicAdd(&g_er2[ra], erp[m][0]); }
            if (rb < n) { atomicAdd(&g_el2[rb], elp[m][1]); atomicAdd(&g_er2[rb], erp[m][1]); }
        }
    }
}

// ================= fused GAT aggregation (batched-index edge loops) =============
__global__ void __launch_bounds__(256) gat1_acc_kernel(float* __restrict__ out_h1, int n) {
    int node = (blockIdx.x * blockDim.x + threadIdx.x) >> 5;
    int lane = threadIdx.x & 31;
    if (node >= n) return;
    const int row0 = g_rowstart[node];
    const int deg  = g_hist[node];
    const int h = lane >> 2;
    float er = (lane < H1h) ? g_er1[node * H1h + lane] : 0.f;

    float ssum = 0.f;
    float a0 = 0.f, a1 = 0.f, a2 = 0.f, a3 = 0.f;

    for (int k0 = 0; k0 < deg; k0 += 32) {
        const int rem = deg - k0;
        const int nb = rem < 32 ? rem : 32;
        int sidx = 0;
        if (lane < rem) sidx = __ldg(&g_ssrc[row0 + k0 + lane]);
#pragma unroll 8
        for (int j = 0; j < nb; j++) {
            int s = __shfl_sync(0xffffffffu, sidx, j);
            float4 f = *(const float4*)(g_ft1 + (size_t)s * C1 + lane * 4);
            float ex = 0.f;
            if (lane < H1h) {
                float v = g_el1[s * H1h + lane] + er;
                v = (v >= 0.f) ? v : SLOPE * v;
                ex = __expf(v);
                ssum += ex;
            }
            float exl = __shfl_sync(0xffffffffu, ex, h);
            a0 = fmaf(f.x, exl, a0);
            a1 = fmaf(f.y, exl, a1);
            a2 = fmaf(f.z, exl, a2);
            a3 = fmaf(f.w, exl, a3);
        }
    }
    float ssl = __shfl_sync(0xffffffffu, ssum, h);
    float inv = (ssl > 0.f) ? 1.f / ssl : 0.f;
    float4 o;
    o.x = fmaxf(a0 * inv, 0.f);
    o.y = fmaxf(a1 * inv, 0.f);
    o.z = fmaxf(a2 * inv, 0.f);
    o.w = fmaxf(a3 * inv, 0.f);
    *(float4*)(out_h1 + (size_t)node * C1 + lane * 4) = o;
}

__global__ void __launch_bounds__(256) gat2_acc_kernel(float* __restrict__ out_h, int n) {
    int node = (blockIdx.x * blockDim.x + threadIdx.x) >> 5;
    int lane = threadIdx.x & 31;
    if (node >= n) return;
    const int row0 = g_rowstart[node];
    const int deg  = g_hist[node];
    const float er = g_er2[node];

    float ssum = 0.f;
    float a0 = 0.f, a1 = 0.f;

    for (int k0 = 0; k0 < deg; k0 += 32) {
        const int rem = deg - k0;
        const int nb = rem < 32 ? rem : 32;
        int sidx = 0;
        float exv = 0.f;
        if (lane < rem) {
            sidx = __ldg(&g_ssrc[row0 + k0 + lane]);
            float v = g_el2[sidx] + er;      // lane-parallel exp precompute
            v = (v >= 0.f) ? v : SLOPE * v;
            exv = __expf(v);
            ssum += exv;
        }
#pragma unroll 4
        for (int j = 0; j < nb; j++) {
            int s = __shfl_sync(0xffffffffu, sidx, j);
            float exl = __shfl_sync(0xffffffffu, exv, j);
            float2 f = *(const float2*)(g_ft2 + (size_t)s * D2 + lane * 2);
            a0 = fmaf(f.x, exl, a0);
            a1 = fmaf(f.y, exl, a1);
        }
    }
#pragma unroll
    for (int off = 16; off >= 1; off >>= 1)
        ssum += __shfl_xor_sync(0xffffffffu, ssum, off);
    float inv = (ssum > 0.f) ? 1.f / ssum : 0.f;
    float2 o;
    o.x = a0 * inv;
    o.y = a1 * inv;
    *(float2*)(out_h + (size_t)node * D2 + lane * 2) = o;
}

// ================= launch =================
extern "C" void kernel_launch(void* const* d_in, const int* in_sizes, int n_in,
                              void* d_out, int out_size) {
    const float* feats = (const float*)d_in[0];
    const int*   src   = (const int*)d_in[1];
    const int*   dst   = (const int*)d_in[2];
    const float* W1    = (const float*)d_in[3];
    const float* al1   = (const float*)d_in[4];
    const float* ar1   = (const float*)d_in[5];
    const float* W2    = (const float*)d_in[6];
    const float* al2   = (const float*)d_in[7];
    const float* ar2   = (const float*)d_in[8];
    float* out = (float*)d_out;

    const int n = in_sizes[0] / DIN;   // 100000
    const int E = in_sizes[1];         // 1600000

    float* out_h1 = out + (size_t)n * DIN;
    float* out_h  = out_h1 + (size_t)n * C1;

    cudaFuncSetAttribute(gemm1_mma_kernel,
                         cudaFuncAttributeMaxDynamicSharedMemorySize, G1_SMEM);

    // ---- fork a side stream: CSR build, then off-critical-path memcpy ----
    cudaStream_t s1;
    cudaEvent_t evFork, evJoin, evCopyDone;
    cudaStreamCreateWithFlags(&s1, cudaStreamNonBlocking);
    cudaEventCreateWithFlags(&evFork, cudaEventDisableTiming);
    cudaEventCreateWithFlags(&evJoin, cudaEventDisableTiming);
    cudaEventCreateWithFlags(&evCopyDone, cudaEventDisableTiming);

    cudaEventRecord(evFork, 0);
    cudaStreamWaitEvent(s1, evFork, 0);

    // side branch: dst-CSR counting sort (+ el2/er2 zero)
    const int nb = (n + SCAN_B - 1) / SCAN_B;
    zero_hist<<<(n + 255) / 256, 256, 0, s1>>>(n);
    hist_kernel<<<(E + 255) / 256, 256, 0, s1>>>(dst, E);
    scanA<<<nb, SCAN_B, 0, s1>>>(n);
    scanB<<<1, 128, 0, s1>>>(nb);
    scanC<<<(n + 255) / 256, 256, 0, s1>>>(n);
    scatter_kernel<<<(E + 255) / 256, 256, 0, s1>>>(src, dst, E);
    cudaEventRecord(evJoin, s1);

    // feats -> out copy: no dependents; overlaps gat/gemm phase; joined at end.
    cudaMemcpyAsync(out, feats, (size_t)n * DIN * sizeof(float),
                    cudaMemcpyDeviceToDevice, s1);
    cudaEventRecord(evCopyDone, s1);

    // main branch: weight split + layer-1 GEMM (+ fused coef1 epilogue)
    splitW_kernel<<<(C1 * DIN + D2 * C1 + 255) / 256, 256>>>(W1, W2);
    gemm1_mma_kernel<<<(n + 127) / 128, 256, G1_SMEM>>>(feats, al1, ar1, n);

    // join: aggregation needs the CSR
    cudaStreamWaitEvent(0, evJoin, 0);
    gat1_acc_kernel<<<(n * 32 + 255) / 256, 256>>>(out_h1, n);

    // ---- layer 2 (coef2 fused into gemm2 epilogue) ----
    gemm2_mma_kernel<<<(n + 127) / 128, 256>>>(out_h1, al2, ar2, n);
    gat2_acc_kernel<<<(n * 32 + 255) / 256, 256>>>(out_h, n);

    // final join of the copy branch (keeps graph capture fully joined)
    cudaStreamWaitEvent(0, evCopyDone, 0);
}